// round 15
// baseline (speedup 1.0000x reference)
#include <cuda_runtime.h>
#include <cuda_bf16.h>
#include <cstdint>

#define NN 50000
#define EE 800000
#define ET (EE + NN)          // edges + self loops
#define F12 448               // 7 heads * 64 ch
#define F3  32

// ---------------- scratch (static device globals; no allocation allowed) ----
__device__ __align__(128) uint32_t g_hb[(size_t)NN * 224];  // layer-1/2 h, bf16x2 packed
__device__ __align__(128) float g_bufC[(size_t)NN * F3];    // layer-3 h (fp32)
__device__ __align__(128) float g_xt[(size_t)NN * 256];     // x, tf32-rounded
__device__ __align__(128) float g_at[(size_t)NN * F12];     // agg out, tf32-rounded
__device__ float g_as[NN * 7];
__device__ float g_ad[NN * 7];
__device__ float g_m[NN * 7];       // softmax running max per (node,head)
__device__ float g_inv[NN * 7];     // 1/denom per (node,head)
__device__ int g_cnt[NN];
__device__ int g_off[NN + 1];
__device__ int g_cur[NN];
__device__ int g_esrc[ET];
// transposed tf32-rounded weights: WT[n*K + k] = W[k*N + n]
__device__ __align__(128) float g_wt1[448 * 256];
__device__ __align__(128) float g_wt2[448 * 448];
__device__ __align__(128) float g_wt3[32 * 448];

// ---------------- helpers --------------------------------------------------
__device__ __forceinline__ float tf32r(float v) {
    uint32_t t;
    asm("cvt.rna.tf32.f32 %0, %1;" : "=r"(t) : "f"(v));
    return __uint_as_float(t);
}
__device__ __forceinline__ uint32_t smem_u32(const void* p) {
    uint32_t a;
    asm("{ .reg .u64 t; cvta.to.shared.u64 t, %1; cvt.u32.u64 %0, t; }" : "=r"(a) : "l"(p));
    return a;
}
__device__ __forceinline__ void cp16(uint32_t dst, const void* src) {
    asm volatile("cp.async.cg.shared.global [%0], [%1], 16;" :: "r"(dst), "l"(src));
}
#define CP_COMMIT() asm volatile("cp.async.commit_group;" ::: "memory")
#define CP_WAIT1()  asm volatile("cp.async.wait_group 1;" ::: "memory")
#define CP_WAIT0()  asm volatile("cp.async.wait_group 0;" ::: "memory")

__device__ __forceinline__ void mma_tf32(float* c, const uint32_t* a, const uint32_t* b) {
    asm volatile(
        "mma.sync.aligned.m16n8k8.row.col.f32.tf32.tf32.f32 "
        "{%0,%1,%2,%3}, {%4,%5,%6,%7}, {%8,%9}, {%0,%1,%2,%3};"
        : "+f"(c[0]), "+f"(c[1]), "+f"(c[2]), "+f"(c[3])
        : "r"(a[0]), "r"(a[1]), "r"(a[2]), "r"(a[3]), "r"(b[0]), "r"(b[1]));
}
__device__ __forceinline__ float2 unpack_bf2(uint32_t p) {
    float2 r;
    r.x = __uint_as_float(p << 16);
    r.y = __uint_as_float(p & 0xffff0000u);
    return r;
}

// ---------------- CSR build ------------------------------------------------
__global__ void zero_cnt_kernel() {
    int i = blockIdx.x * blockDim.x + threadIdx.x;
    if (i < NN) g_cnt[i] = 0;
}
__global__ void hist_kernel(const int* __restrict__ ei) {
    int e = blockIdx.x * blockDim.x + threadIdx.x;
    if (e >= ET) return;
    int dst = (e < EE) ? ei[EE + e] : (e - EE);
    atomicAdd(&g_cnt[dst], 1);
}
// single-block scan: per-thread serial chunk + shuffle block scan (3 barriers)
__global__ void scan_kernel() {
    __shared__ int ws[32];
    const int tid = threadIdx.x;                    // 1024 threads
    const int CHK = (NN + 1023) / 1024;             // 49
    const int b0 = tid * CHK;
    int lsum = 0;
    for (int i = 0; i < CHK; i++) {
        int idx = b0 + i;
        lsum += (idx < NN) ? g_cnt[idx] : 0;
    }
    const int lane = tid & 31, wrp = tid >> 5;
    int inc = lsum;
#pragma unroll
    for (int o = 1; o < 32; o <<= 1) {
        int t = __shfl_up_sync(0xffffffffu, inc, o);
        if (lane >= o) inc += t;
    }
    if (lane == 31) ws[wrp] = inc;
    __syncthreads();
    if (wrp == 0) {
        int v = ws[lane];
#pragma unroll
        for (int o = 1; o < 32; o <<= 1) {
            int t = __shfl_up_sync(0xffffffffu, v, o);
            if (lane >= o) v += t;
        }
        ws[lane] = v;
    }
    __syncthreads();
    int off = (inc - lsum) + (wrp ? ws[wrp - 1] : 0);   // exclusive prefix
    int run = off;
    for (int i = 0; i < CHK; i++) {
        int idx = b0 + i;
        if (idx < NN) {
            g_off[idx] = run;
            g_cur[idx] = run;
            run += g_cnt[idx];
        }
    }
    if (tid == 1023) g_off[NN] = run;
}
__global__ void scatter_kernel(const int* __restrict__ ei) {
    int e = blockIdx.x * blockDim.x + threadIdx.x;
    if (e >= ET) return;
    int src, dst;
    if (e < EE) { src = ei[e]; dst = ei[EE + e]; }
    else        { src = e - EE; dst = src; }
    int p = atomicAdd(&g_cur[dst], 1);
    g_esrc[p] = src;
}

// ---------------- W transpose + tf32 round ---------------------------------
__global__ void convW_kernel(const float* __restrict__ W, float* __restrict__ T,
                             int K, int Ncol) {
    int idx = blockIdx.x * blockDim.x + threadIdx.x;
    if (idx >= K * Ncol) return;
    int n = idx / K, k = idx % K;
    T[idx] = tf32r(W[(size_t)k * Ncol + n]);
}
__global__ void convX_kernel(const float* __restrict__ x, float* __restrict__ xt, int total4) {
    int i = blockIdx.x * blockDim.x + threadIdx.x;
    if (i >= total4) return;
    float4 v = *(const float4*)(x + (size_t)i * 4);
    v.x = tf32r(v.x); v.y = tf32r(v.y); v.z = tf32r(v.z); v.w = tf32r(v.w);
    *(float4*)(xt + (size_t)i * 4) = v;
}

// ---------------- TF32 GEMM, BK=32, cp.async 2-stage, 3 CTAs/SM ------------
// Block: 256 thr = 8 warps (4 in M x 2 in N). BM=128, BN=CH (one head).
// BF16OUT: pack C into bf16x2 (g_hb) for the aggregation gather.
template<int CH, bool BF16OUT>
__global__ void __launch_bounds__(256)
gemm_gat(const float* __restrict__ Ag, const float* __restrict__ BT,
         float* __restrict__ Cf, uint32_t* __restrict__ Cb,
         float* __restrict__ as_o, float* __restrict__ ad_o,
         const float* __restrict__ a_src, const float* __restrict__ a_dst,
         int M, int K, int NH) {
    constexpr int BK = 32;
    constexpr int SP = 36;                 // smem row stride in floats (pad)
    constexpr int CHW = CH / 2;
    constexpr int NT = CH / 16;
    constexpr int ASZ = 128 * SP;
    constexpr int BSZ = CH * SP;
    constexpr int STAGE = ASZ + BSZ;
    extern __shared__ char smem[];
    float* sm = (float*)smem;
    float* asbuf = sm + 2 * STAGE;         // [128][2]
    float* adbuf = asbuf + 128 * 2;

    const int tid = threadIdx.x, wid = tid >> 5, lane = tid & 31;
    const int wm = wid & 3, wn = wid >> 2;
    const int gid = lane >> 2, tig = lane & 3;
    const int bm = blockIdx.y * 128;
    const int h = blockIdx.x;

    const float* bsrc = BT + (size_t)h * CH * K;
    const uint32_t sb0 = smem_u32(sm);
    const int lr = tid >> 3, lq = tid & 7;   // 8 cp16 units per 32-float row

    float c[2][NT][4];
#pragma unroll
    for (int i = 0; i < 2; i++)
#pragma unroll
        for (int j = 0; j < NT; j++)
#pragma unroll
            for (int q = 0; q < 4; q++) c[i][j][q] = 0.f;

    const int nch = K >> 5;

    auto load_stage = [&](int st, int ch) {
        const int k0 = ch << 5;
        const uint32_t aB = sb0 + (uint32_t)st * STAGE * 4;
        const uint32_t bB = aB + ASZ * 4;
#pragma unroll
        for (int it = 0; it < 4; it++) {         // A: 128 rows x 32 floats
            int r = lr + it * 32;
            size_t gidx = (size_t)min(bm + r, M - 1) * K + k0 + lq * 4;
            cp16(aB + (uint32_t)(r * SP + lq * 4) * 4, Ag + gidx);
        }
#pragma unroll
        for (int it = 0; it < CH / 32; it++) {   // B: CH rows x 32 floats
            int n = lr + it * 32;
            size_t gidx = (size_t)n * K + k0 + lq * 4;
            cp16(bB + (uint32_t)(n * SP + lq * 4) * 4, bsrc + gidx);
        }
    };

    load_stage(0, 0);
    CP_COMMIT();

    for (int ch = 0; ch < nch; ch++) {
        if (ch + 1 < nch) { load_stage((ch + 1) & 1, ch + 1); CP_COMMIT(); CP_WAIT1(); }
        else              { CP_WAIT0(); }
        __syncthreads();
        const float* As = sm + (ch & 1) * STAGE;
        const float* Bs = As + ASZ;
        const uint32_t* As32 = (const uint32_t*)As;
        const uint32_t* Bs32 = (const uint32_t*)Bs;
        const int ar0 = (wm * 32 + gid) * SP;
        const int bn0 = (wn * CHW + gid) * SP;
#pragma unroll
        for (int ks = 0; ks < BK / 8; ks++) {
            const int kb = ks * 8 + tig;
            uint32_t a[2][4], b[NT][2];
#pragma unroll
            for (int mt = 0; mt < 2; mt++) {
                int r = ar0 + mt * 16 * SP + kb;
                a[mt][0] = As32[r];
                a[mt][1] = As32[r + 8 * SP];
                a[mt][2] = As32[r + 4];
                a[mt][3] = As32[r + 8 * SP + 4];
            }
#pragma unroll
            for (int nt = 0; nt < NT; nt++) {
                int n = bn0 + nt * 8 * SP + kb;
                b[nt][0] = Bs32[n];
                b[nt][1] = Bs32[n + 4];
            }
#pragma unroll
            for (int mt = 0; mt < 2; mt++)
#pragma unroll
                for (int nt = 0; nt < NT; nt++)
                    mma_tf32(c[mt][nt], a[mt], b[nt]);
        }
        __syncthreads();
    }

    // ---- epilogue: write C (bf16x2 or fp32) + fused alpha dots ----
    float pa[2][2], pd[2][2];
#pragma unroll
    for (int mt = 0; mt < 2; mt++)
#pragma unroll
        for (int r2 = 0; r2 < 2; r2++) { pa[mt][r2] = 0.f; pd[mt][r2] = 0.f; }
#pragma unroll
    for (int mt = 0; mt < 2; mt++) {
#pragma unroll
        for (int nt = 0; nt < NT; nt++) {
            int col = wn * CHW + nt * 8 + tig * 2;
            int row0 = bm + wm * 32 + mt * 16 + gid;
            float s0 = a_src[h * CH + col], s1 = a_src[h * CH + col + 1];
            float d0 = a_dst[h * CH + col], d1 = a_dst[h * CH + col + 1];
            pa[mt][0] += c[mt][nt][0] * s0 + c[mt][nt][1] * s1;
            pd[mt][0] += c[mt][nt][0] * d0 + c[mt][nt][1] * d1;
            pa[mt][1] += c[mt][nt][2] * s0 + c[mt][nt][3] * s1;
            pd[mt][1] += c[mt][nt][2] * d0 + c[mt][nt][3] * d1;
            if (BF16OUT) {
                int ci = wn * (CHW / 2) + nt * 4 + tig;     // bf16x2 index (col/2)
                if (row0 < M) {
                    __nv_bfloat162 p0 = __floats2bfloat162_rn(c[mt][nt][0], c[mt][nt][1]);
                    Cb[((size_t)row0 * NH + h) * (CH / 2) + ci] = *(uint32_t*)&p0;
                }
                if (row0 + 8 < M) {
                    __nv_bfloat162 p1 = __floats2bfloat162_rn(c[mt][nt][2], c[mt][nt][3]);
                    Cb[((size_t)(row0 + 8) * NH + h) * (CH / 2) + ci] = *(uint32_t*)&p1;
                }
            } else {
                if (row0 < M)
                    *(float2*)&Cf[(size_t)row0 * NH * CH + h * CH + col] =
                        make_float2(c[mt][nt][0], c[mt][nt][1]);
                if (row0 + 8 < M)
                    *(float2*)&Cf[(size_t)(row0 + 8) * NH * CH + h * CH + col] =
                        make_float2(c[mt][nt][2], c[mt][nt][3]);
            }
        }
    }
#pragma unroll
    for (int mt = 0; mt < 2; mt++)
#pragma unroll
        for (int r2 = 0; r2 < 2; r2++) {
#pragma unroll
            for (int o = 1; o < 4; o <<= 1) {
                pa[mt][r2] += __shfl_xor_sync(0xffffffffu, pa[mt][r2], o);
                pd[mt][r2] += __shfl_xor_sync(0xffffffffu, pd[mt][r2], o);
            }
            if (tig == 0) {
                int rl = wm * 32 + mt * 16 + r2 * 8 + gid;
                asbuf[rl * 2 + wn] = pa[mt][r2];
                adbuf[rl * 2 + wn] = pd[mt][r2];
            }
        }
    __syncthreads();
    if (tid < 128) {
        int row = bm + tid;
        if (row < M) {
            as_o[row * NH + h] = asbuf[tid * 2] + asbuf[tid * 2 + 1];
            ad_o[row * NH + h] = adbuf[tid * 2] + adbuf[tid * 2 + 1];
        }
    }
}

// ---------------- softmax stats: pass 1 (lane-parallel online softmax) -----
// one warp per (dst,head); lanes stride the edge list; warp-combine states.
template<int NH>
__global__ void stats_kernel(const float* __restrict__ as, const float* __restrict__ ad,
                             float* __restrict__ gm, float* __restrict__ ginv) {
    int gw = (blockIdx.x * blockDim.x + threadIdx.x) >> 5;
    int lane = threadIdx.x & 31;
    if (gw >= NN * NH) return;
    int n = gw / NH, hh = gw % NH;
    int beg = g_off[n], end = g_off[n + 1];
    float adn = ad[n * NH + hh];
    float m = -1e30f, d = 0.f;
    for (int i = beg + lane; i < end; i += 32) {
        int s = g_esrc[i];
        float e = as[s * NH + hh] + adn;
        e = e > 0.f ? e : 0.2f * e;                 // leaky relu
        if (e <= m) d += __expf(e - m);
        else { d = d * __expf(m - e) + 1.f; m = e; }
    }
#pragma unroll
    for (int o = 16; o; o >>= 1) {
        float mo = __shfl_xor_sync(0xffffffffu, m, o);
        float do_ = __shfl_xor_sync(0xffffffffu, d, o);
        float mn = fmaxf(m, mo);
        d = d * __expf(m - mn) + do_ * __expf(mo - mn);
        m = mn;
    }
    if (lane == 0) { gm[gw] = m; ginv[gw] = 1.f / (d + 1e-16f); }
}

// ---------------- accum: pass 2 (no loop-carried deps), bf16 gather --------
// one warp per (dst,head); lane owns channels 2*lane, 2*lane+1 (bf16x2 load)
template<int NH, bool RELU>
__global__ void accum64_kernel(const uint32_t* __restrict__ hb, const float* __restrict__ as,
                               const float* __restrict__ ad, const float* __restrict__ gm,
                               const float* __restrict__ ginv, const float* __restrict__ bias,
                               float* __restrict__ oa) {
    int gw = (blockIdx.x * blockDim.x + threadIdx.x) >> 5;
    int lane = threadIdx.x & 31;
    if (gw >= NN * NH) return;
    int n = gw / NH, hh = gw % NH;
    int beg = g_off[n], end = g_off[n + 1];
    float adn = ad[gw];
    float m = gm[gw], inv = ginv[gw];
    float ax = 0.f, ay = 0.f;
#pragma unroll 2
    for (int i = beg; i < end; i++) {
        int s = g_esrc[i];
        float e = as[s * NH + hh] + adn;
        e = e > 0.f ? e : 0.2f * e;                 // leaky relu
        float w = __expf(e - m);
        uint32_t p = __ldg(hb + ((size_t)s * NH + hh) * 32 + lane);
        float2 hv = unpack_bf2(p);
        ax += w * hv.x;
        ay += w * hv.y;
    }
    float r0 = ax * inv + bias[hh * 64 + 2 * lane];
    float r1 = ay * inv + bias[hh * 64 + 2 * lane + 1];
    if (RELU) { r0 = fmaxf(r0, 0.f); r1 = fmaxf(r1, 0.f); }
    size_t idx = (size_t)n * NH * 64 + hh * 64 + 2 * lane;
    *(float2*)(oa + idx) = make_float2(tf32r(r0), tf32r(r1));
}

// ---------------- layer-3 accum + fused log_softmax (C=32, NH=1, fp32) ----
__global__ void accum32_kernel(const float* __restrict__ h, const float* __restrict__ as,
                               const float* __restrict__ ad, const float* __restrict__ gm,
                               const float* __restrict__ ginv, const float* __restrict__ bias,
                               float* __restrict__ out) {
    int gw = (blockIdx.x * blockDim.x + threadIdx.x) >> 5;
    int lane = threadIdx.x & 31;
    if (gw >= NN) return;
    int n = gw;
    int beg = g_off[n], end = g_off[n + 1];
    float adn = ad[n];
    float m = gm[n], inv = ginv[n];
    float acc = 0.f;
#pragma unroll 2
    for (int i = beg; i < end; i++) {
        int s = g_esrc[i];
        float e = as[s] + adn;
        e = e > 0.f ? e : 0.2f * e;
        float w = __expf(e - m);
        acc += w * __ldg(h + (size_t)s * 32 + lane);
    }
    float r = acc * inv + bias[lane];
    float mx = r;
#pragma unroll
    for (int o = 16; o; o >>= 1) mx = fmaxf(mx, __shfl_xor_sync(0xffffffffu, mx, o));
    float ex = __expf(r - mx);
    float sm = ex;
#pragma unroll
    for (int o = 16; o; o >>= 1) sm += __shfl_xor_sync(0xffffffffu, sm, o);
    out[(size_t)n * 32 + lane] = r - mx - logf(sm);
}

// ---------------- launch ---------------------------------------------------
extern "C" void kernel_launch(void* const* d_in, const int* in_sizes, int n_in,
                              void* d_out, int out_size) {
    const float* x   = (const float*)d_in[0];
    const int*   ei  = (const int*)d_in[1];
    const float* W1  = (const float*)d_in[2];
    const float* a1s = (const float*)d_in[3];
    const float* a1d = (const float*)d_in[4];
    const float* b1  = (const float*)d_in[5];
    const float* W2  = (const float*)d_in[6];
    const float* a2s = (const float*)d_in[7];
    const float* a2d = (const float*)d_in[8];
    const float* b2  = (const float*)d_in[9];
    const float* W3  = (const float*)d_in[10];
    const float* a3s = (const float*)d_in[11];
    const float* a3d = (const float*)d_in[12];
    const float* b3  = (const float*)d_in[13];
    float* out = (float*)d_out;

    float *bufC, *pas, *pad_, *pm, *pinv, *xt, *at, *wt1, *wt2, *wt3;
    uint32_t* hb;
    cudaGetSymbolAddress((void**)&hb, g_hb);
    cudaGetSymbolAddress((void**)&bufC, g_bufC);
    cudaGetSymbolAddress((void**)&pas, g_as);
    cudaGetSymbolAddress((void**)&pad_, g_ad);
    cudaGetSymbolAddress((void**)&pm, g_m);
    cudaGetSymbolAddress((void**)&pinv, g_inv);
    cudaGetSymbolAddress((void**)&xt, g_xt);
    cudaGetSymbolAddress((void**)&at, g_at);
    cudaGetSymbolAddress((void**)&wt1, g_wt1);
    cudaGetSymbolAddress((void**)&wt2, g_wt2);
    cudaGetSymbolAddress((void**)&wt3, g_wt3);

    // smem: 2 stages of (A 128*36 + B CH*36) floats + 512 floats for alpha
    const int SMEM64 = 2 * (128 * 36 + 64 * 36) * 4 + 2 * 128 * 2 * 4;  // 57344
    const int SMEM32 = 2 * (128 * 36 + 32 * 36) * 4 + 2 * 128 * 2 * 4;  // 48128
    cudaFuncSetAttribute(gemm_gat<64, true>, cudaFuncAttributeMaxDynamicSharedMemorySize, SMEM64);
    cudaFuncSetAttribute(gemm_gat<32, false>, cudaFuncAttributeMaxDynamicSharedMemorySize, SMEM32);

    const int MB = (NN + 127) / 128;              // 391
    const int wb12 = (NN * 7 * 32 + 255) / 256;
    const int wb3  = (NN * 1 * 32 + 255) / 256;

    // slots 0-2: gemm1 prerequisites; slot 3: gemm1 (ncu capture target)
    convX_kernel<<<(NN * 256 / 4 + 255) / 256, 256>>>(x, xt, NN * 256 / 4);
    convW_kernel<<<(448 * 256 + 255) / 256, 256>>>(W1, wt1, 256, 448);
    zero_cnt_kernel<<<(NN + 255) / 256, 256>>>();
    gemm_gat<64, true><<<dim3(7, MB), 256, SMEM64>>>(xt, wt1, nullptr, hb, pas, pad_, a1s, a1d, NN, 256, 7);

    // CSR build + remaining weight prep
    hist_kernel<<<(ET + 255) / 256, 256>>>(ei);
    scan_kernel<<<1, 1024>>>();
    scatter_kernel<<<(ET + 255) / 256, 256>>>(ei);
    convW_kernel<<<(448 * 448 + 255) / 256, 256>>>(W2, wt2, 448, 448);
    convW_kernel<<<(32 * 448 + 255) / 256, 256>>>(W3, wt3, 448, 32);

    // ---- layer 1 agg (two-pass) ----
    stats_kernel<7><<<wb12, 256>>>(pas, pad_, pm, pinv);
    accum64_kernel<7, true><<<wb12, 256>>>(hb, pas, pad_, pm, pinv, b1, at);

    // ---- layer 2 ----
    gemm_gat<64, true><<<dim3(7, MB), 256, SMEM64>>>(at, wt2, nullptr, hb, pas, pad_, a2s, a2d, NN, 448, 7);
    stats_kernel<7><<<wb12, 256>>>(pas, pad_, pm, pinv);
    accum64_kernel<7, true><<<wb12, 256>>>(hb, pas, pad_, pm, pinv, b2, at);

    // ---- layer 3 (+ fused log_softmax) ----
    gemm_gat<32, false><<<dim3(1, MB), 256, SMEM32>>>(at, wt3, bufC, nullptr, pas, pad_, a3s, a3d, NN, 448, 1);
    stats_kernel<1><<<wb3, 256>>>(pas, pad_, pm, pinv);
    accum32_kernel<<<wb3, 256>>>(bufC, pas, pad_, pm, pinv, b3, out);
}

// round 17
// speedup vs baseline: 1.0254x; 1.0254x over previous
#include <cuda_runtime.h>
#include <cuda_bf16.h>
#include <cstdint>

#define NN 50000
#define EE 800000
#define ET (EE + NN)          // edges + self loops
#define F12 448               // 7 heads * 64 ch
#define F3  32

// ---------------- scratch (static device globals; no allocation allowed) ----
__device__ __align__(128) uint32_t g_hb[(size_t)NN * 224];  // layer-1/2 h, bf16x2 packed
__device__ __align__(128) float g_bufC[(size_t)NN * F3];    // layer-3 h (fp32)
__device__ __align__(128) float g_xt[(size_t)NN * 256];     // x, tf32-rounded
__device__ __align__(128) float g_at[(size_t)NN * F12];     // agg out, tf32-rounded
__device__ float g_as[NN * 7];
__device__ float g_ad[NN * 7];
__device__ int g_cnt[NN];
__device__ int g_off[NN + 1];
__device__ int g_cur[NN];
__device__ int g_esrc[ET];
// transposed tf32-rounded weights: WT[n*K + k] = W[k*N + n]
__device__ __align__(128) float g_wt1[448 * 256];
__device__ __align__(128) float g_wt2[448 * 448];
__device__ __align__(128) float g_wt3[32 * 448];

// ---------------- helpers --------------------------------------------------
__device__ __forceinline__ float tf32r(float v) {
    uint32_t t;
    asm("cvt.rna.tf32.f32 %0, %1;" : "=r"(t) : "f"(v));
    return __uint_as_float(t);
}
__device__ __forceinline__ uint32_t smem_u32(const void* p) {
    uint32_t a;
    asm("{ .reg .u64 t; cvta.to.shared.u64 t, %1; cvt.u32.u64 %0, t; }" : "=r"(a) : "l"(p));
    return a;
}
__device__ __forceinline__ void cp16(uint32_t dst, const void* src) {
    asm volatile("cp.async.cg.shared.global [%0], [%1], 16;" :: "r"(dst), "l"(src));
}
#define CP_COMMIT() asm volatile("cp.async.commit_group;" ::: "memory")
#define CP_WAIT1()  asm volatile("cp.async.wait_group 1;" ::: "memory")
#define CP_WAIT0()  asm volatile("cp.async.wait_group 0;" ::: "memory")

__device__ __forceinline__ void mma_tf32(float* c, const uint32_t* a, const uint32_t* b) {
    asm volatile(
        "mma.sync.aligned.m16n8k8.row.col.f32.tf32.tf32.f32 "
        "{%0,%1,%2,%3}, {%4,%5,%6,%7}, {%8,%9}, {%0,%1,%2,%3};"
        : "+f"(c[0]), "+f"(c[1]), "+f"(c[2]), "+f"(c[3])
        : "r"(a[0]), "r"(a[1]), "r"(a[2]), "r"(a[3]), "r"(b[0]), "r"(b[1]));
}
__device__ __forceinline__ float2 unpack_bf2(uint32_t p) {
    float2 r;
    r.x = __uint_as_float(p << 16);
    r.y = __uint_as_float(p & 0xffff0000u);
    return r;
}

// ---------------- CSR build ------------------------------------------------
__global__ void zero_cnt_kernel() {
    int i = blockIdx.x * blockDim.x + threadIdx.x;
    if (i < NN) g_cnt[i] = 0;
}
__global__ void hist_kernel(const int* __restrict__ ei) {
    int e = blockIdx.x * blockDim.x + threadIdx.x;
    if (e >= ET) return;
    int dst = (e < EE) ? ei[EE + e] : (e - EE);
    atomicAdd(&g_cnt[dst], 1);
}
// single-block scan: per-thread serial chunk + shuffle block scan (3 barriers)
__global__ void scan_kernel() {
    __shared__ int ws[32];
    const int tid = threadIdx.x;                    // 1024 threads
    const int CHK = (NN + 1023) / 1024;             // 49
    const int b0 = tid * CHK;
    int lsum = 0;
    for (int i = 0; i < CHK; i++) {
        int idx = b0 + i;
        lsum += (idx < NN) ? g_cnt[idx] : 0;
    }
    const int lane = tid & 31, wrp = tid >> 5;
    int inc = lsum;
#pragma unroll
    for (int o = 1; o < 32; o <<= 1) {
        int t = __shfl_up_sync(0xffffffffu, inc, o);
        if (lane >= o) inc += t;
    }
    if (lane == 31) ws[wrp] = inc;
    __syncthreads();
    if (wrp == 0) {
        int v = ws[lane];
#pragma unroll
        for (int o = 1; o < 32; o <<= 1) {
            int t = __shfl_up_sync(0xffffffffu, v, o);
            if (lane >= o) v += t;
        }
        ws[lane] = v;
    }
    __syncthreads();
    int off = (inc - lsum) + (wrp ? ws[wrp - 1] : 0);   // exclusive prefix
    int run = off;
    for (int i = 0; i < CHK; i++) {
        int idx = b0 + i;
        if (idx < NN) {
            g_off[idx] = run;
            g_cur[idx] = run;
            run += g_cnt[idx];
        }
    }
    if (tid == 1023) g_off[NN] = run;
}
__global__ void scatter_kernel(const int* __restrict__ ei) {
    int e = blockIdx.x * blockDim.x + threadIdx.x;
    if (e >= ET) return;
    int src, dst;
    if (e < EE) { src = ei[e]; dst = ei[EE + e]; }
    else        { src = e - EE; dst = src; }
    int p = atomicAdd(&g_cur[dst], 1);
    g_esrc[p] = src;
}

// ---------------- W transpose + tf32 round ---------------------------------
__global__ void convW_kernel(const float* __restrict__ W, float* __restrict__ T,
                             int K, int Ncol) {
    int idx = blockIdx.x * blockDim.x + threadIdx.x;
    if (idx >= K * Ncol) return;
    int n = idx / K, k = idx % K;
    T[idx] = tf32r(W[(size_t)k * Ncol + n]);
}
__global__ void convX_kernel(const float* __restrict__ x, float* __restrict__ xt, int total4) {
    int i = blockIdx.x * blockDim.x + threadIdx.x;
    if (i >= total4) return;
    float4 v = *(const float4*)(x + (size_t)i * 4);
    v.x = tf32r(v.x); v.y = tf32r(v.y); v.z = tf32r(v.z); v.w = tf32r(v.w);
    *(float4*)(xt + (size_t)i * 4) = v;
}

// ---------------- TF32 GEMM, BK=32, cp.async 2-stage, 3 CTAs/SM ------------
// Block: 256 thr = 8 warps (4 in M x 2 in N). BM=128, BN=CH (one head).
// BF16OUT: pack C into bf16x2 (g_hb) for the aggregation gather.
template<int CH, bool BF16OUT>
__global__ void __launch_bounds__(256)
gemm_gat(const float* __restrict__ Ag, const float* __restrict__ BT,
         float* __restrict__ Cf, uint32_t* __restrict__ Cb,
         float* __restrict__ as_o, float* __restrict__ ad_o,
         const float* __restrict__ a_src, const float* __restrict__ a_dst,
         int M, int K, int NH) {
    constexpr int BK = 32;
    constexpr int SP = 36;                 // smem row stride in floats (pad)
    constexpr int CHW = CH / 2;
    constexpr int NT = CH / 16;
    constexpr int ASZ = 128 * SP;
    constexpr int BSZ = CH * SP;
    constexpr int STAGE = ASZ + BSZ;
    extern __shared__ char smem[];
    float* sm = (float*)smem;
    float* asbuf = sm + 2 * STAGE;         // [128][2]
    float* adbuf = asbuf + 128 * 2;

    const int tid = threadIdx.x, wid = tid >> 5, lane = tid & 31;
    const int wm = wid & 3, wn = wid >> 2;
    const int gid = lane >> 2, tig = lane & 3;
    const int bm = blockIdx.y * 128;
    const int h = blockIdx.x;

    const float* bsrc = BT + (size_t)h * CH * K;
    const uint32_t sb0 = smem_u32(sm);
    const int lr = tid >> 3, lq = tid & 7;   // 8 cp16 units per 32-float row

    float c[2][NT][4];
#pragma unroll
    for (int i = 0; i < 2; i++)
#pragma unroll
        for (int j = 0; j < NT; j++)
#pragma unroll
            for (int q = 0; q < 4; q++) c[i][j][q] = 0.f;

    const int nch = K >> 5;

    auto load_stage = [&](int st, int ch) {
        const int k0 = ch << 5;
        const uint32_t aB = sb0 + (uint32_t)st * STAGE * 4;
        const uint32_t bB = aB + ASZ * 4;
#pragma unroll
        for (int it = 0; it < 4; it++) {         // A: 128 rows x 32 floats
            int r = lr + it * 32;
            size_t gidx = (size_t)min(bm + r, M - 1) * K + k0 + lq * 4;
            cp16(aB + (uint32_t)(r * SP + lq * 4) * 4, Ag + gidx);
        }
#pragma unroll
        for (int it = 0; it < CH / 32; it++) {   // B: CH rows x 32 floats
            int n = lr + it * 32;
            size_t gidx = (size_t)n * K + k0 + lq * 4;
            cp16(bB + (uint32_t)(n * SP + lq * 4) * 4, bsrc + gidx);
        }
    };

    load_stage(0, 0);
    CP_COMMIT();

    for (int ch = 0; ch < nch; ch++) {
        if (ch + 1 < nch) { load_stage((ch + 1) & 1, ch + 1); CP_COMMIT(); CP_WAIT1(); }
        else              { CP_WAIT0(); }
        __syncthreads();
        const float* As = sm + (ch & 1) * STAGE;
        const float* Bs = As + ASZ;
        const uint32_t* As32 = (const uint32_t*)As;
        const uint32_t* Bs32 = (const uint32_t*)Bs;
        const int ar0 = (wm * 32 + gid) * SP;
        const int bn0 = (wn * CHW + gid) * SP;
#pragma unroll
        for (int ks = 0; ks < BK / 8; ks++) {
            const int kb = ks * 8 + tig;
            uint32_t a[2][4], b[NT][2];
#pragma unroll
            for (int mt = 0; mt < 2; mt++) {
                int r = ar0 + mt * 16 * SP + kb;
                a[mt][0] = As32[r];
                a[mt][1] = As32[r + 8 * SP];
                a[mt][2] = As32[r + 4];
                a[mt][3] = As32[r + 8 * SP + 4];
            }
#pragma unroll
            for (int nt = 0; nt < NT; nt++) {
                int n = bn0 + nt * 8 * SP + kb;
                b[nt][0] = Bs32[n];
                b[nt][1] = Bs32[n + 4];
            }
#pragma unroll
            for (int mt = 0; mt < 2; mt++)
#pragma unroll
                for (int nt = 0; nt < NT; nt++)
                    mma_tf32(c[mt][nt], a[mt], b[nt]);
        }
        __syncthreads();
    }

    // ---- epilogue: write C (bf16x2 or fp32) + fused alpha dots ----
    float pa[2][2], pd[2][2];
#pragma unroll
    for (int mt = 0; mt < 2; mt++)
#pragma unroll
        for (int r2 = 0; r2 < 2; r2++) { pa[mt][r2] = 0.f; pd[mt][r2] = 0.f; }
#pragma unroll
    for (int mt = 0; mt < 2; mt++) {
#pragma unroll
        for (int nt = 0; nt < NT; nt++) {
            int col = wn * CHW + nt * 8 + tig * 2;
            int row0 = bm + wm * 32 + mt * 16 + gid;
            float s0 = a_src[h * CH + col], s1 = a_src[h * CH + col + 1];
            float d0 = a_dst[h * CH + col], d1 = a_dst[h * CH + col + 1];
            pa[mt][0] += c[mt][nt][0] * s0 + c[mt][nt][1] * s1;
            pd[mt][0] += c[mt][nt][0] * d0 + c[mt][nt][1] * d1;
            pa[mt][1] += c[mt][nt][2] * s0 + c[mt][nt][3] * s1;
            pd[mt][1] += c[mt][nt][2] * d0 + c[mt][nt][3] * d1;
            if (BF16OUT) {
                int ci = wn * (CHW / 2) + nt * 4 + tig;     // bf16x2 index (col/2)
                if (row0 < M) {
                    __nv_bfloat162 p0 = __floats2bfloat162_rn(c[mt][nt][0], c[mt][nt][1]);
                    Cb[((size_t)row0 * NH + h) * (CH / 2) + ci] = *(uint32_t*)&p0;
                }
                if (row0 + 8 < M) {
                    __nv_bfloat162 p1 = __floats2bfloat162_rn(c[mt][nt][2], c[mt][nt][3]);
                    Cb[((size_t)(row0 + 8) * NH + h) * (CH / 2) + ci] = *(uint32_t*)&p1;
                }
            } else {
                if (row0 < M)
                    *(float2*)&Cf[(size_t)row0 * NH * CH + h * CH + col] =
                        make_float2(c[mt][nt][0], c[mt][nt][1]);
                if (row0 + 8 < M)
                    *(float2*)&Cf[(size_t)(row0 + 8) * NH * CH + h * CH + col] =
                        make_float2(c[mt][nt][2], c[mt][nt][3]);
            }
        }
    }
#pragma unroll
    for (int mt = 0; mt < 2; mt++)
#pragma unroll
        for (int r2 = 0; r2 < 2; r2++) {
#pragma unroll
            for (int o = 1; o < 4; o <<= 1) {
                pa[mt][r2] += __shfl_xor_sync(0xffffffffu, pa[mt][r2], o);
                pd[mt][r2] += __shfl_xor_sync(0xffffffffu, pd[mt][r2], o);
            }
            if (tig == 0) {
                int rl = wm * 32 + mt * 16 + r2 * 8 + gid;
                asbuf[rl * 2 + wn] = pa[mt][r2];
                adbuf[rl * 2 + wn] = pd[mt][r2];
            }
        }
    __syncthreads();
    if (tid < 128) {
        int row = bm + tid;
        if (row < M) {
            as_o[row * NH + h] = asbuf[tid * 2] + asbuf[tid * 2 + 1];
            ad_o[row * NH + h] = adbuf[tid * 2] + adbuf[tid * 2 + 1];
        }
    }
}

// ---------------- gather-side online-softmax aggregation (C=64) ------------
// SINGLE PASS (R14 structure — measured best), bf16x2 feature gather (R15 win)
// one warp per (dst,head); lane owns channels 2*lane, 2*lane+1; lazy rescale.
template<int NH, bool RELU>
__global__ void agg64_kernel(const uint32_t* __restrict__ hb, const float* __restrict__ as,
                             const float* __restrict__ ad, const float* __restrict__ bias,
                             float* __restrict__ oa) {
    int gw = (blockIdx.x * blockDim.x + threadIdx.x) >> 5;
    int lane = threadIdx.x & 31;
    if (gw >= NN * NH) return;
    int n = gw / NH, hh = gw % NH;
    int beg = g_off[n], end = g_off[n + 1];
    float adn = ad[gw];
    float ax = 0.f, ay = 0.f;
    float m = -1e30f, dsum = 0.f;
    for (int i = beg; i < end; i++) {
        int s = g_esrc[i];
        float e = as[s * NH + hh] + adn;
        e = e > 0.f ? e : 0.2f * e;                 // leaky relu
        uint32_t p = __ldg(hb + ((size_t)s * NH + hh) * 32 + lane);
        float2 hv = unpack_bf2(p);
        if (e <= m) {                               // warp-uniform branch
            float w = __expf(e - m);
            dsum += w;
            ax += w * hv.x; ay += w * hv.y;
        } else {
            float sc = __expf(m - e);
            dsum = dsum * sc + 1.f;
            ax = ax * sc + hv.x; ay = ay * sc + hv.y;
            m = e;
        }
    }
    float inv = 1.f / (dsum + 1e-16f);
    float r0 = ax * inv + bias[hh * 64 + 2 * lane];
    float r1 = ay * inv + bias[hh * 64 + 2 * lane + 1];
    if (RELU) { r0 = fmaxf(r0, 0.f); r1 = fmaxf(r1, 0.f); }
    size_t idx = (size_t)n * NH * 64 + hh * 64 + 2 * lane;
    *(float2*)(oa + idx) = make_float2(tf32r(r0), tf32r(r1));
}

// ---------------- layer-3 aggregation + fused log_softmax (C=32, NH=1) ----
__global__ void agg32_kernel(const float* __restrict__ h, const float* __restrict__ as,
                             const float* __restrict__ ad, const float* __restrict__ bias,
                             float* __restrict__ out) {
    int gw = (blockIdx.x * blockDim.x + threadIdx.x) >> 5;
    int lane = threadIdx.x & 31;
    if (gw >= NN) return;
    int n = gw;
    int beg = g_off[n], end = g_off[n + 1];
    float adn = ad[n];
    float acc = 0.f, m = -1e30f, dsum = 0.f;
    for (int i = beg; i < end; i++) {
        int s = g_esrc[i];
        float e = as[s] + adn;
        e = e > 0.f ? e : 0.2f * e;
        float hv = __ldg(h + (size_t)s * 32 + lane);
        if (e <= m) {
            float w = __expf(e - m);
            dsum += w; acc += w * hv;
        } else {
            float sc = __expf(m - e);
            dsum = dsum * sc + 1.f;
            acc = acc * sc + hv;
            m = e;
        }
    }
    float inv = 1.f / (dsum + 1e-16f);
    float r = acc * inv + bias[lane];
    float mx = r;
#pragma unroll
    for (int o = 16; o; o >>= 1) mx = fmaxf(mx, __shfl_xor_sync(0xffffffffu, mx, o));
    float ex = __expf(r - mx);
    float sm = ex;
#pragma unroll
    for (int o = 16; o; o >>= 1) sm += __shfl_xor_sync(0xffffffffu, sm, o);
    out[(size_t)n * 32 + lane] = r - mx - logf(sm);
}

// ---------------- launch ---------------------------------------------------
extern "C" void kernel_launch(void* const* d_in, const int* in_sizes, int n_in,
                              void* d_out, int out_size) {
    const float* x   = (const float*)d_in[0];
    const int*   ei  = (const int*)d_in[1];
    const float* W1  = (const float*)d_in[2];
    const float* a1s = (const float*)d_in[3];
    const float* a1d = (const float*)d_in[4];
    const float* b1  = (const float*)d_in[5];
    const float* W2  = (const float*)d_in[6];
    const float* a2s = (const float*)d_in[7];
    const float* a2d = (const float*)d_in[8];
    const float* b2  = (const float*)d_in[9];
    const float* W3  = (const float*)d_in[10];
    const float* a3s = (const float*)d_in[11];
    const float* a3d = (const float*)d_in[12];
    const float* b3  = (const float*)d_in[13];
    float* out = (float*)d_out;

    float *bufC, *pas, *pad_, *xt, *at, *wt1, *wt2, *wt3;
    uint32_t* hb;
    cudaGetSymbolAddress((void**)&hb, g_hb);
    cudaGetSymbolAddress((void**)&bufC, g_bufC);
    cudaGetSymbolAddress((void**)&pas, g_as);
    cudaGetSymbolAddress((void**)&pad_, g_ad);
    cudaGetSymbolAddress((void**)&xt, g_xt);
    cudaGetSymbolAddress((void**)&at, g_at);
    cudaGetSymbolAddress((void**)&wt1, g_wt1);
    cudaGetSymbolAddress((void**)&wt2, g_wt2);
    cudaGetSymbolAddress((void**)&wt3, g_wt3);

    // smem: 2 stages of (A 128*36 + B CH*36) floats + 512 floats for alpha
    const int SMEM64 = 2 * (128 * 36 + 64 * 36) * 4 + 2 * 128 * 2 * 4;  // 57344
    const int SMEM32 = 2 * (128 * 36 + 32 * 36) * 4 + 2 * 128 * 2 * 4;  // 48128
    cudaFuncSetAttribute(gemm_gat<64, true>, cudaFuncAttributeMaxDynamicSharedMemorySize, SMEM64);
    cudaFuncSetAttribute(gemm_gat<32, false>, cudaFuncAttributeMaxDynamicSharedMemorySize, SMEM32);

    const int MB = (NN + 127) / 128;              // 391
    const int wb12 = (NN * 7 * 32 + 255) / 256;
    const int wb3  = (NN * 1 * 32 + 255) / 256;

    // slots 0-2: gemm1 prerequisites; slot 3: gemm1 (ncu capture target)
    convX_kernel<<<(NN * 256 / 4 + 255) / 256, 256>>>(x, xt, NN * 256 / 4);
    convW_kernel<<<(448 * 256 + 255) / 256, 256>>>(W1, wt1, 256, 448);
    zero_cnt_kernel<<<(NN + 255) / 256, 256>>>();
    gemm_gat<64, true><<<dim3(7, MB), 256, SMEM64>>>(xt, wt1, nullptr, hb, pas, pad_, a1s, a1d, NN, 256, 7);

    // CSR build + remaining weight prep
    hist_kernel<<<(ET + 255) / 256, 256>>>(ei);
    scan_kernel<<<1, 1024>>>();
    scatter_kernel<<<(ET + 255) / 256, 256>>>(ei);
    convW_kernel<<<(448 * 448 + 255) / 256, 256>>>(W2, wt2, 448, 448);
    convW_kernel<<<(32 * 448 + 255) / 256, 256>>>(W3, wt3, 448, 32);

    // ---- layer 1 agg ----
    agg64_kernel<7, true><<<wb12, 256>>>(hb, pas, pad_, b1, at);

    // ---- layer 2 ----
    gemm_gat<64, true><<<dim3(7, MB), 256, SMEM64>>>(at, wt2, nullptr, hb, pas, pad_, a2s, a2d, NN, 448, 7);
    agg64_kernel<7, true><<<wb12, 256>>>(hb, pas, pad_, b2, at);

    // ---- layer 3 (+ fused log_softmax) ----
    gemm_gat<32, false><<<dim3(1, MB), 256, SMEM32>>>(at, wt3, bufC, nullptr, pas, pad_, a3s, a3d, NN, 448, 1);
    agg32_kernel<<<wb3, 256>>>(bufC, pas, pad_, b3, out);
}